// round 17
// baseline (speedup 1.0000x reference)
#include <cuda_runtime.h>
#include <cuda_bf16.h>
#include <cuda_fp16.h>

typedef unsigned long long u64;
typedef unsigned int u32;

#define NPTS   65536
#define CCH    64
#define NSMP   16
#define CSW    8
#define EPSV   1e-5f
#define NBW    4   // warps per block in fused kernel
#define PPW    4   // points per warp (looped)
#define GROWS  512 // rows per gemm block
#define GCHK   8   // chunks per gemm block

// ---------------- f32x2 helpers ----------------
__device__ __forceinline__ u64 pk2(float a, float b) {
    u64 r; asm("mov.b64 %0, {%1, %2};" : "=l"(r) : "f"(a), "f"(b)); return r;
}
__device__ __forceinline__ void upk2(u64 v, float& a, float& b) {
    asm("mov.b64 {%0, %1}, %2;" : "=f"(a), "=f"(b) : "l"(v));
}
__device__ __forceinline__ u64 ffma2(u64 a, u64 b, u64 c) {
    u64 d; asm("fma.rn.f32x2 %0, %1, %2, %3;" : "=l"(d) : "l"(a), "l"(b), "l"(c)); return d;
}
__device__ __forceinline__ u32 f22h(float a, float b) {
    __half2 h = __floats2half2_rn(a, b);
    return *reinterpret_cast<u32*>(&h);
}
__device__ __forceinline__ u32 smem_u32(const void* p) {
    return (u32)__cvta_generic_to_shared(p);
}
__device__ __forceinline__ void h4_to_f22(u64 h4, u64& loPair, u64& hiPair) {
    u32 lo = (u32)h4, hi = (u32)(h4 >> 32);
    __half2 hlo = *reinterpret_cast<__half2*>(&lo);
    __half2 hhi = *reinterpret_cast<__half2*>(&hi);
    float2 flo = __half22float2(hlo), fhi = __half22float2(hhi);
    loPair = pk2(flo.x, flo.y);
    hiPair = pk2(fhi.x, fhi.y);
}
// ---------------- half2-as-u32 helpers ----------------
__device__ __forceinline__ u32 hfma2u(u32 a, u32 b, u32 c) {
    __half2 r = __hfma2(*(__half2*)&a, *(__half2*)&b, *(__half2*)&c);
    return *(u32*)&r;
}
__device__ __forceinline__ u32 hadd2u(u32 a, u32 b) {
    __half2 r = __hadd2(*(__half2*)&a, *(__half2*)&b);
    return *(u32*)&r;
}
__device__ __forceinline__ u32 hrelu2u(u32 a) {
    __half2 z = __floats2half2_rn(0.f, 0.f);
    __half2 r = __hmax2(*(__half2*)&a, z);
    return *(u32*)&r;
}

// ---------------- scratch tables (fp16, L2-resident) ----------------
__device__ u64        g_xq [NPTS * CCH / 4];   // xq quads
__device__ ulonglong2 g_xkv[NPTS * 16];        // per row: 16 x {xk quad, xv quad}
__device__ float4     g_p4 [NPTS];             // padded coords

// =====================================================================
// Kernel 1: xq/xk/xv = x @ W^T + b via fp16 tensor-core MMA.
// 512 rows/block in 8 chunks -> single wave (128 blocks on 148 SMs).
// B-fragments once; x loads software-pipelined.
// =====================================================================
__global__ __launch_bounds__(256) void gemm_qkv_mma(
    const float* __restrict__ x, const float* __restrict__ p,
    const float* __restrict__ Wq, const float* __restrict__ bq,
    const float* __restrict__ Wk, const float* __restrict__ bk,
    const float* __restrict__ Wv, const float* __restrict__ bv)
{
    __shared__ __align__(16) __half sx[64][72];
    __shared__ __align__(16) u32 sxq [64][32];   // staging, swizzled
    __shared__ __align__(16) u32 sxkv[64][64];   // staging, swizzled

    const int tid  = threadIdx.x;
    const int warp = tid >> 5;
    const int lane = tid & 31;
    const int row0 = blockIdx.x * GROWS;

    // p4 table slice (512 rows)
    #pragma unroll
    for (int e = 0; e < GROWS / 256; ++e) {
        const int r = tid + e * 256;
        const float* pr = &p[(row0 + r) * 3];
        g_p4[row0 + r] = make_float4(pr[0], pr[1], pr[2], 0.f);
    }

    // ---- B fragments + biases: built once per block ----
    const int n0  = warp * 8;
    const int nn  = n0 + (lane >> 2);
    const int kfr = 2 * (lane & 3);

    const float* Ws[3] = {Wq, Wk, Wv};
    const float* Bs[3] = {bq, bk, bv};
    u32 bf[3][4][2];
    float bsx[3], bsy[3];
    #pragma unroll
    for (int m = 0; m < 3; ++m) {
        #pragma unroll
        for (int ks = 0; ks < 4; ++ks) {
            const float* wr = &Ws[m][nn * 64 + ks * 16 + kfr];
            float2 wa = *(const float2*)&wr[0];
            float2 wb = *(const float2*)&wr[8];
            bf[m][ks][0] = f22h(wa.x, wa.y);
            bf[m][ks][1] = f22h(wb.x, wb.y);
        }
        float2 bb = *(const float2*)&Bs[m][n0 + kfr];
        bsx[m] = bb.x; bsy[m] = bb.y;
    }

    const int pp   = (n0 + kfr) >> 1;   // 0..31
    const int qq   = pp >> 1;           // quad 0..15
    const int half = pp & 1;

    const int lr  = tid & 63;           // load row within chunk
    const int lkb = (tid >> 6) * 16;    // load col base

    // prologue: issue chunk-0 loads
    float4 v0, v1, v2, v3;
    {
        const float* xr = &x[(row0 + lr) * 64 + lkb];
        v0 = *(const float4*)&xr[0];
        v1 = *(const float4*)&xr[4];
        v2 = *(const float4*)&xr[8];
        v3 = *(const float4*)&xr[12];
    }

    for (int ck = 0; ck < GCHK; ++ck) {
        const int rowc = row0 + ck * 64;

        // store current chunk's x (held in regs) into smem
        {
            uint4 h0 = make_uint4(f22h(v0.x, v0.y), f22h(v0.z, v0.w),
                                  f22h(v1.x, v1.y), f22h(v1.z, v1.w));
            uint4 h1 = make_uint4(f22h(v2.x, v2.y), f22h(v2.z, v2.w),
                                  f22h(v3.x, v3.y), f22h(v3.z, v3.w));
            *(uint4*)&sx[lr][lkb]     = h0;
            *(uint4*)&sx[lr][lkb + 8] = h1;
        }
        __syncthreads();

        // issue NEXT chunk's loads now; latency overlaps the MMA below
        if (ck < GCHK - 1) {
            const float* xr = &x[(rowc + 64 + lr) * 64 + lkb];
            v0 = *(const float4*)&xr[0];
            v1 = *(const float4*)&xr[4];
            v2 = *(const float4*)&xr[8];
            v3 = *(const float4*)&xr[12];
        }

        #pragma unroll
        for (int rt = 0; rt < 4; ++rt) {
            const int r0 = rt * 16;
            u32 afr[4][4];
            const int arow  = r0 + (lane & 15);
            const int acolb = (lane >> 4) << 3;
            #pragma unroll
            for (int ks = 0; ks < 4; ++ks) {
                u32 ad = smem_u32(&sx[arow][ks * 16 + acolb]);
                asm volatile("ldmatrix.sync.aligned.m8n8.x4.shared.b16 {%0,%1,%2,%3}, [%4];"
                    : "=r"(afr[ks][0]), "=r"(afr[ks][1]), "=r"(afr[ks][2]), "=r"(afr[ks][3])
                    : "r"(ad));
            }
            const int rA = r0 + (lane >> 2);   // local rows 0..63
            const int rB = rA + 8;
            #pragma unroll
            for (int m = 0; m < 3; ++m) {
                float d0 = 0.f, d1 = 0.f, d2 = 0.f, d3 = 0.f;
                #pragma unroll
                for (int ks = 0; ks < 4; ++ks) {
                    asm volatile("mma.sync.aligned.m16n8k16.row.col.f32.f16.f16.f32 "
                        "{%0,%1,%2,%3}, {%4,%5,%6,%7}, {%8,%9}, {%0,%1,%2,%3};"
                        : "+f"(d0), "+f"(d1), "+f"(d2), "+f"(d3)
                        : "r"(afr[ks][0]), "r"(afr[ks][1]), "r"(afr[ks][2]), "r"(afr[ks][3]),
                          "r"(bf[m][ks][0]), "r"(bf[m][ks][1]));
                }
                d0 += bsx[m]; d1 += bsy[m]; d2 += bsx[m]; d3 += bsy[m];
                if (m == 0) {
                    sxq[rA][pp ^ ((rA & 7) << 2)] = f22h(d0, d1);
                    sxq[rB][pp ^ ((rB & 7) << 2)] = f22h(d2, d3);
                } else {
                    const int col = qq * 4 + ((m == 1) ? 0 : 2) + half;
                    sxkv[rA][col ^ ((rA & 7) << 2)] = f22h(d0, d1);
                    sxkv[rB][col ^ ((rB & 7) << 2)] = f22h(d2, d3);
                }
            }
        }
        __syncthreads();

        // coalesced writes: xq (512 uint4), xkv (1024 uint4)
        {
            u32* oq = (u32*)g_xq;
            #pragma unroll
            for (int e = 0; e < 2; ++e) {
                int idx4 = tid + e * 256;
                int r = idx4 >> 3;
                int i = idx4 & 7;
                int colb = (i * 4) ^ ((r & 7) << 2);
                uint4 v = *(uint4*)&sxq[r][colb];
                *(uint4*)&oq[(rowc + r) * 32 + i * 4] = v;
            }
            u32* okv = (u32*)g_xkv;
            #pragma unroll
            for (int e = 0; e < 4; ++e) {
                int idx4 = tid + e * 256;
                int r = idx4 >> 4;
                int i = idx4 & 15;
                int colb = (i * 4) ^ ((r & 7) << 2);
                uint4 v = *(uint4*)&sxkv[r][colb];
                *(uint4*)&okv[(rowc + r) * 64 + i * 4] = v;
            }
        }
    }
}

// =====================================================================
// Kernel 2: fused point-transformer. (round-16, unchanged)
// =====================================================================
__global__ void __launch_bounds__(128, 8) fused_pt(
    const int*   __restrict__ idx,
    const float* __restrict__ Wp1, const float* __restrict__ bp1,
    const float* __restrict__ pg,  const float* __restrict__ pb,
    const float* __restrict__ pm,  const float* __restrict__ pv,
    const float* __restrict__ Wp2, const float* __restrict__ bp2,
    const float* __restrict__ wg1, const float* __restrict__ wb1,
    const float* __restrict__ wm1, const float* __restrict__ wv1,
    const float* __restrict__ Ww1, const float* __restrict__ bw1,
    const float* __restrict__ wg2, const float* __restrict__ wb2,
    const float* __restrict__ wm2, const float* __restrict__ wv2,
    const float* __restrict__ Ww2, const float* __restrict__ bw2,
    float* __restrict__ out)
{
    __shared__ float  sWp1[9], sbp1v[3], spa[3], spbv[3];
    __shared__ __align__(16) uint4   sBc[32][5];   // per-lane Phase B constants
    __shared__ __align__(16) __half  ssw16 [NBW][16][72];
    __shared__ __align__(16) __half  svpe16[NBW][16][64];
    __shared__ __align__(16) uint4   stvh  [NBW][16];
    __shared__ __align__(16) float   swl   [NBW][16][8];

    const int tid = threadIdx.x;
    if (tid < 9) sWp1[tid] = Wp1[tid];
    if (tid < 3) {
        sbp1v[tid] = bp1[tid];
        float a = pg[tid] * rsqrtf(pv[tid] + EPSV);
        spa[tid] = a; spbv[tid] = pb[tid] - pm[tid] * a;
    }
    if (tid < 32) {
        const int nfr = tid >> 2;
        const int kfr = 2 * (tid & 3);
        u32 bfB[8];
        #pragma unroll
        for (int ch = 0; ch < 4; ++ch) {
            const float* wr = &Ww1[nfr * 64 + ch * 16 + kfr];
            float2 wa = *(const float2*)&wr[0];
            float2 wb = *(const float2*)&wr[8];
            bfB[2 * ch]     = f22h(wa.x, wa.y);
            bfB[2 * ch + 1] = f22h(wb.x, wb.y);
        }
        float2 w2p  = *(const float2*)&Ww2[nfr * 8 + kfr];
        float2 bw1p = *(const float2*)&bw1[kfr];
        float2 g2p  = *(const float2*)&wg2[kfr];
        float2 v2p  = *(const float2*)&wv2[kfr];
        float2 b2p  = *(const float2*)&wb2[kfr];
        float2 m2p  = *(const float2*)&wm2[kfr];
        float2 bb2p = *(const float2*)&bw2[kfr];
        float tA = g2p.x * rsqrtf(v2p.x + EPSV);
        float tB = g2p.y * rsqrtf(v2p.y + EPSV);
        sBc[tid][0] = make_uint4(bfB[0], bfB[1], bfB[2], bfB[3]);
        sBc[tid][1] = make_uint4(bfB[4], bfB[5], bfB[6], bfB[7]);
        sBc[tid][2] = make_uint4(f22h(w2p.x, w2p.y),
                                 __float_as_uint(bw1p.x),
                                 __float_as_uint(bw1p.y),
                                 __float_as_uint(tA));
        sBc[tid][3] = make_uint4(__float_as_uint(tB),
                                 __float_as_uint(b2p.x - m2p.x * tA),
                                 __float_as_uint(b2p.y - m2p.y * tB),
                                 __float_as_uint(bb2p.x));
        sBc[tid][4] = make_uint4(__float_as_uint(bb2p.y), 0u, 0u, 0u);
    }
    __syncthreads();

    const int w    = tid >> 5;
    const int lane = tid & 31;
    const int q    = lane & 15;
    const int sub  = lane >> 4;
    const int c0   = 4 * q;

    float4 wpr0 = *(const float4*)&Wp2[c0 * 3];
    float4 wpr1 = *(const float4*)&Wp2[c0 * 3 + 4];
    float4 wpr2 = *(const float4*)&Wp2[c0 * 3 + 8];
    const u32 wpA0 = f22h(wpr0.x, wpr0.w);
    const u32 wpA1 = f22h(wpr0.y, wpr1.x);
    const u32 wpA2 = f22h(wpr0.z, wpr1.y);
    const u32 wpB0 = f22h(wpr1.z, wpr2.y);
    const u32 wpB1 = f22h(wpr1.w, wpr2.z);
    const u32 wpB2 = f22h(wpr2.x, wpr2.w);
    float4 bpv = *(const float4*)&bp2[c0];
    const u32 bpA = f22h(bpv.x, bpv.y), bpB = f22h(bpv.z, bpv.w);
    float4 g1 = *(const float4*)&wg1[c0];
    float4 b1 = *(const float4*)&wb1[c0];
    float4 m1 = *(const float4*)&wm1[c0];
    float4 v1 = *(const float4*)&wv1[c0];
    float a0f = g1.x * rsqrtf(v1.x + EPSV);
    float a1f = g1.y * rsqrtf(v1.y + EPSV);
    float a2f = g1.z * rsqrtf(v1.z + EPSV);
    float a3f = g1.w * rsqrtf(v1.w + EPSV);
    const u32 a1A = f22h(a0f, a1f), a1B = f22h(a2f, a3f);
    const u32 b1A = f22h(b1.x - m1.x * a0f, b1.y - m1.y * a1f);
    const u32 b1B = f22h(b1.z - m1.z * a2f, b1.w - m1.w * a3f);
    const u32 na1A = a1A ^ 0x80008000u;   // -a1 (half2 sign flip)
    const u32 na1B = a1B ^ 0x80008000u;

    const int nfr = lane >> 2;
    const int kfr = 2 * (lane & 3);
    const int nbase = blockIdx.x * (NBW * PPW) + w * PPW;

    for (int pt = 0; pt < PPW; ++pt) {
        const int n = nbase + pt;

        if (lane < 16) {
            int j = idx[n * 16 + lane];
            float4 pn = g_p4[n];
            float4 pj = g_p4[j];
            float prx = pj.x - pn.x;
            float pry = pj.y - pn.y;
            float prz = pj.z - pn.z;
            float u0 = prx * sWp1[0] + pry * sWp1[1] + prz * sWp1[2] + sbp1v[0];
            float u1 = prx * sWp1[3] + pry * sWp1[4] + prz * sWp1[5] + sbp1v[1];
            float u2 = prx * sWp1[6] + pry * sWp1[7] + prz * sWp1[8] + sbp1v[2];
            float t0 = fmaxf(0.f, fmaf(u0, spa[0], spbv[0]));
            float t1 = fmaxf(0.f, fmaf(u1, spa[1], spbv[1]));
            float t2 = fmaxf(0.f, fmaf(u2, spa[2], spbv[2]));
            stvh[w][lane] = make_uint4(f22h(t0, t0), f22h(t1, t1), f22h(t2, t2), (u32)j);
        }
        __syncwarp();

        {
            u64 xqq = g_xq[n * 16 + q];
            const u32 xqA = (u32)xqq, xqB = (u32)(xqq >> 32);
            const u32 nb1A = hfma2u(xqA, na1A, b1A);
            const u32 nb1B = hfma2u(xqB, na1B, b1B);

            #pragma unroll
            for (int hb = 0; hb < 2; ++hb) {
                uint4 tv[4];
                ulonglong2 kv[4];
                #pragma unroll
                for (int i = 0; i < 4; ++i) {
                    const int kk = 8 * hb + 2 * i + sub;
                    tv[i] = stvh[w][kk];
                    kv[i] = g_xkv[(int)tv[i].w * 16 + q];
                }
                #pragma unroll
                for (int i = 0; i < 4; ++i) {
                    const int kk = 8 * hb + 2 * i + sub;
                    u32 kA = (u32)kv[i].x, kB = (u32)(kv[i].x >> 32);
                    u32 vA = (u32)kv[i].y, vB = (u32)(kv[i].y >> 32);
                    u32 peA = hfma2u(wpA0, tv[i].x, hfma2u(wpA1, tv[i].y, hfma2u(wpA2, tv[i].z, bpA)));
                    u32 peB = hfma2u(wpB0, tv[i].x, hfma2u(wpB1, tv[i].y, hfma2u(wpB2, tv[i].z, bpB)));
                    u32 sA2 = hadd2u(kA, peA);             // xk + pe
                    u32 sB2 = hadd2u(kB, peB);
                    u32 wA  = hrelu2u(hfma2u(sA2, a1A, nb1A));
                    u32 wB  = hrelu2u(hfma2u(sB2, a1B, nb1B));
                    *(u64*)&ssw16[w][kk][c0]  = (u64)wA | ((u64)wB << 32);
                    u32 vpA = hadd2u(vA, peA);
                    u32 vpB = hadd2u(vB, peB);
                    *(u64*)&svpe16[w][kk][c0] = (u64)vpA | ((u64)vpB << 32);
                }
            }
        }
        __syncwarp();

        {
            uint4 cb0 = sBc[lane][0];
            uint4 cb1 = sBc[lane][1];
            uint4 cb2 = sBc[lane][2];
            uint4 cb3 = sBc[lane][3];
            uint4 cb4 = sBc[lane][4];
            const u32 bW2f = cb2.x;
            const float cbw1A = __uint_as_float(cb2.y);
            const float cbw1B = __uint_as_float(cb2.z);
            const float ca2A  = __uint_as_float(cb2.w);
            const float ca2B  = __uint_as_float(cb3.x);
            const float cb2A  = __uint_as_float(cb3.y);
            const float cb2B  = __uint_as_float(cb3.z);
            const float cbw2A = __uint_as_float(cb3.w);
            const float cbw2B = __uint_as_float(cb4.x);

            u32 afr[4][4];
            const int arow = lane & 15;
            const int acol = (lane >> 4) << 3;
            #pragma unroll
            for (int ch = 0; ch < 4; ++ch) {
                u32 ad = smem_u32(&ssw16[w][arow][ch * 16 + acol]);
                asm volatile("ldmatrix.sync.aligned.m8n8.x4.shared.b16 {%0,%1,%2,%3}, [%4];"
                    : "=r"(afr[ch][0]), "=r"(afr[ch][1]), "=r"(afr[ch][2]), "=r"(afr[ch][3])
                    : "r"(ad));
            }
            float d0 = 0.f, d1 = 0.f, d2 = 0.f, d3 = 0.f;
            asm volatile("mma.sync.aligned.m16n8k16.row.col.f32.f16.f16.f32 "
                "{%0,%1,%2,%3}, {%4,%5,%6,%7}, {%8,%9}, {%0,%1,%2,%3};"
                : "+f"(d0), "+f"(d1), "+f"(d2), "+f"(d3)
                : "r"(afr[0][0]), "r"(afr[0][1]), "r"(afr[0][2]), "r"(afr[0][3]),
                  "r"(cb0.x), "r"(cb0.y));
            asm volatile("mma.sync.aligned.m16n8k16.row.col.f32.f16.f16.f32 "
                "{%0,%1,%2,%3}, {%4,%5,%6,%7}, {%8,%9}, {%0,%1,%2,%3};"
                : "+f"(d0), "+f"(d1), "+f"(d2), "+f"(d3)
                : "r"(afr[1][0]), "r"(afr[1][1]), "r"(afr[1][2]), "r"(afr[1][3]),
                  "r"(cb0.z), "r"(cb0.w));
            asm volatile("mma.sync.aligned.m16n8k16.row.col.f32.f16.f16.f32 "
                "{%0,%1,%2,%3}, {%4,%5,%6,%7}, {%8,%9}, {%0,%1,%2,%3};"
                : "+f"(d0), "+f"(d1), "+f"(d2), "+f"(d3)
                : "r"(afr[2][0]), "r"(afr[2][1]), "r"(afr[2][2]), "r"(afr[2][3]),
                  "r"(cb1.x), "r"(cb1.y));
            asm volatile("mma.sync.aligned.m16n8k16.row.col.f32.f16.f16.f32 "
                "{%0,%1,%2,%3}, {%4,%5,%6,%7}, {%8,%9}, {%0,%1,%2,%3};"
                : "+f"(d0), "+f"(d1), "+f"(d2), "+f"(d3)
                : "r"(afr[3][0]), "r"(afr[3][1]), "r"(afr[3][2]), "r"(afr[3][3]),
                  "r"(cb1.z), "r"(cb1.w));

            float h0 = fmaxf(0.f, fmaf(d0 + cbw1A, ca2A, cb2A));
            float h1 = fmaxf(0.f, fmaf(d1 + cbw1B, ca2B, cb2B));
            float h2 = fmaxf(0.f, fmaf(d2 + cbw1A, ca2A, cb2A));
            float h3 = fmaxf(0.f, fmaf(d3 + cbw1B, ca2B, cb2B));
            u32 ha0 = f22h(h0, h1), ha1 = f22h(h2, h3);
            float l0 = 0.f, l1 = 0.f, l2 = 0.f, l3 = 0.f;
            asm volatile("mma.sync.aligned.m16n8k8.row.col.f32.f16.f16.f32 "
                "{%0,%1,%2,%3}, {%4,%5}, {%6}, {%0,%1,%2,%3};"
                : "+f"(l0), "+f"(l1), "+f"(l2), "+f"(l3)
                : "r"(ha0), "r"(ha1), "r"(bW2f));
            l0 += cbw2A; l1 += cbw2B; l2 += cbw2A; l3 += cbw2B;

            float mA = fmaxf(l0, l2), mB = fmaxf(l1, l3);
            #pragma unroll
            for (int dlt = 4; dlt <= 16; dlt <<= 1) {
                mA = fmaxf(mA, __shfl_xor_sync(0xffffffffu, mA, dlt));
                mB = fmaxf(mB, __shfl_xor_sync(0xffffffffu, mB, dlt));
            }
            float e0 = __expf(l0 - mA), e1 = __expf(l1 - mB);
            float e2 = __expf(l2 - mA), e3 = __expf(l3 - mB);
            float sA = e0 + e2, sB = e1 + e3;
            #pragma unroll
            for (int dlt = 4; dlt <= 16; dlt <<= 1) {
                sA += __shfl_xor_sync(0xffffffffu, sA, dlt);
                sB += __shfl_xor_sync(0xffffffffu, sB, dlt);
            }
            float iA = 1.f / sA, iB = 1.f / sB;
            *(u64*)&swl[w][nfr][kfr]     = pk2(e0 * iA, e1 * iB);
            *(u64*)&swl[w][nfr + 8][kfr] = pk2(e2 * iA, e3 * iB);
        }
        __syncwarp();

        {
            const int csq = c0 & 7;

            u64 acc0 = 0ull, acc1 = 0ull;
            #pragma unroll
            for (int it = 0; it < 8; ++it) {
                const int kk = 2 * it + sub;
                u64 vq = *(const u64*)&svpe16[w][kk][c0];
                u64 vA, vB; h4_to_f22(vq, vA, vB);
                ulonglong2 g2 = *(const ulonglong2*)&swl[w][kk][csq];
                acc0 = ffma2(vA, g2.x, acc0);
                acc1 = ffma2(vB, g2.y, acc1);
            }
            float o0, o1, o2, o3;
            upk2(acc0, o0, o1); upk2(acc1, o2, o3);
            o0 += __shfl_xor_sync(0xffffffffu, o0, 16);
            o1 += __shfl_xor_sync(0xffffffffu, o1, 16);
            o2 += __shfl_xor_sync(0xffffffffu, o2, 16);
            o3 += __shfl_xor_sync(0xffffffffu, o3, 16);
            if (sub == 0)
                *(float4*)&out[n * 64 + c0] = make_float4(o0, o1, o2, o3);
        }
        __syncwarp();
    }
}

// =====================================================================
extern "C" void kernel_launch(void* const* d_in, const int* in_sizes, int n_in,
                              void* d_out, int out_size)
{
    const float* p   = (const float*)d_in[0];
    const float* x   = (const float*)d_in[1];
    const int*   idx = (const int*)  d_in[2];
    const float* Wq  = (const float*)d_in[3];
    const float* bq  = (const float*)d_in[4];
    const float* Wk  = (const float*)d_in[5];
    const float* bk  = (const float*)d_in[6];
    const float* Wv  = (const float*)d_in[7];
    const float* bv  = (const float*)d_in[8];
    const float* Wp1 = (const float*)d_in[9];
    const float* bp1 = (const float*)d_in[10];
    const float* pg  = (const float*)d_in[11];
    const float* pb  = (const float*)d_in[12];
    const float* pm  = (const float*)d_in[13];
    const float* pv  = (const float*)d_in[14];
    const float* Wp2 = (const float*)d_in[15];
    const float* bp2 = (const float*)d_in[16];
    const float* wg1 = (const float*)d_in[17];
    const float* wb1 = (const float*)d_in[18];
    const float* wm1 = (const float*)d_in[19];
    const float* wv1 = (const float*)d_in[20];
    const float* Ww1 = (const float*)d_in[21];
    const float* bw1 = (const float*)d_in[22];
    const float* wg2 = (const float*)d_in[23];
    const float* wb2 = (const float*)d_in[24];
    const float* wm2 = (const float*)d_in[25];
    const float* wv2 = (const float*)d_in[26];
    const float* Ww2 = (const float*)d_in[27];
    const float* bw2 = (const float*)d_in[28];
    float* out = (float*)d_out;

    gemm_qkv_mma<<<NPTS / GROWS, 256>>>(x, p, Wq, bq, Wk, bk, Wv, bv);
    fused_pt<<<NPTS / (NBW * PPW), 128>>>(idx, Wp1, bp1, pg, pb, pm, pv, Wp2, bp2,
                                          wg1, wb1, wm1, wv1, Ww1, bw1,
                                          wg2, wb2, wm2, wv2, Ww2, bw2, out);
}